// round 9
// baseline (speedup 1.0000x reference)
#include <cuda_runtime.h>
#include <cuda_fp16.h>
#include <cstdint>

// DigitCapsules dynamic routing, GB300 sm_103a
// B=256, C=10, I=1152, DI=8, DO=16, 3 routing iterations.
//
// R9: route grid was the bottleneck all along (256 blocks on 148 SMs ->
// ~17 warps/SM regardless of regs). Now: 4-CTA cluster per batch element
// (grid=1024, 64-reg body, 3 CTAs/SM -> ~30 warps/SM). Each CTA handles a
// 288-i quarter straight from gmem; per-iteration cross-CTA s-reduction via
// gmem atomics + threadfence + cluster.sync; every CTA squashes locally.
// g_s zeroed by each cluster's q0 CTA before the first barrier.

#define BSZ  256
#define CCL  10
#define ICAP 1152
#define DOV  16
#define DIV  8
#define QSPL 4                 // CTAs per cluster (i-quarters)
#define ISL  (ICAP / QSPL)     // 288
#define NT   (ISL / 32)        // 9 tiles of 32 capsules

typedef unsigned long long ull;

__device__ __align__(256) __half g_uhat[(size_t)BSZ * CCL * ICAP * DOV]; // 94.4 MB
__device__ __align__(256) float g_s[3 * BSZ * CCL * DOV];                // 480 KB

// ---------------- packed f32x2 helpers (exact fp32 SIMD-2) ------------------
static __device__ __forceinline__ ull pack2(float x, float y) {
    ull r; asm("mov.b64 %0, {%1, %2};" : "=l"(r) : "f"(x), "f"(y)); return r;
}
static __device__ __forceinline__ void unpack2(ull v, float& x, float& y) {
    asm("mov.b64 {%0, %1}, %2;" : "=f"(x), "=f"(y) : "l"(v));
}
static __device__ __forceinline__ ull fma2(ull a, ull b, ull c) {
    ull d; asm("fma.rn.f32x2 %0, %1, %2, %3;" : "=l"(d) : "l"(a), "l"(b), "l"(c));
    return d;
}
static __device__ __forceinline__ ull mul2(ull a, ull b) {
    ull d; asm("mul.rn.f32x2 %0, %1, %2;" : "=l"(d) : "l"(a), "l"(b)); return d;
}
static __device__ __forceinline__ ull add2(ull a, ull b) {
    ull d; asm("add.rn.f32x2 %0, %1, %2;" : "=l"(d) : "l"(a), "l"(b)); return d;
}
static __device__ __forceinline__ ull h2f2(__half2 h) {
    float2 f = __half22float2(h);
    return pack2(f.x, f.y);
}
static __device__ __forceinline__ unsigned int pack_h2(float a, float b) {
    __half2 h = __floats2half2_rn(a, b);
    return *reinterpret_cast<unsigned int*>(&h);
}
static __device__ __forceinline__ void cluster_barrier() {
    asm volatile("barrier.cluster.arrive.aligned;" ::: "memory");
    asm volatile("barrier.cluster.wait.aligned;"   ::: "memory");
}

// ---------------------------------------------------------------------------
// K_uhat (R4 version, proven 34us): u_hat[b,c,i,:] = W[c,i] @ x[b,i]
// grid = I (block per input capsule), 256 threads = b.
// ---------------------------------------------------------------------------
__global__ __launch_bounds__(256) void uhat_kernel(
    const float* __restrict__ x, const float* __restrict__ W)
{
    const int i = blockIdx.x;
    const int b = threadIdx.x;

    __shared__ float4 Ws[CCL * DOV * 2];   // 5120 B

    for (int f = threadIdx.x; f < CCL * DOV * 2; f += 256) {
        int c = f >> 5, rem = f & 31, d = rem >> 1, h = rem & 1;
        Ws[f] = *reinterpret_cast<const float4*>(
            W + ((((size_t)c * ICAP + i) * DOV) + d) * DIV + h * 4);
    }

    const float* xp = x + (size_t)b * (ICAP * DIV) + (size_t)i * DIV;
    const float4 x0 = *reinterpret_cast<const float4*>(xp);
    const float4 x1 = *reinterpret_cast<const float4*>(xp + 4);

    __syncthreads();

    __half* up = g_uhat + (size_t)b * (CCL * ICAP * DOV) + (size_t)i * DOV;

    #pragma unroll
    for (int c = 0; c < CCL; c++) {
        float r[DOV];
        #pragma unroll
        for (int d = 0; d < DOV; d++) {
            float4 w0 = Ws[c * 32 + d * 2];
            float4 w1 = Ws[c * 32 + d * 2 + 1];
            float v = w0.x * x0.x;
            v = fmaf(w0.y, x0.y, v); v = fmaf(w0.z, x0.z, v); v = fmaf(w0.w, x0.w, v);
            v = fmaf(w1.x, x1.x, v); v = fmaf(w1.y, x1.y, v);
            v = fmaf(w1.z, x1.z, v); v = fmaf(w1.w, x1.w, v);
            r[d] = v;
        }
        uint4 q0, q1;
        q0.x = pack_h2(r[0],  r[1]);  q0.y = pack_h2(r[2],  r[3]);
        q0.z = pack_h2(r[4],  r[5]);  q0.w = pack_h2(r[6],  r[7]);
        q1.x = pack_h2(r[8],  r[9]);  q1.y = pack_h2(r[10], r[11]);
        q1.z = pack_h2(r[12], r[13]); q1.w = pack_h2(r[14], r[15]);
        __half* o = up + (size_t)c * (ICAP * DOV);
        *reinterpret_cast<uint4*>(o)     = q0;
        *reinterpret_cast<uint4*>(o + 8) = q1;
    }
}

// ---------------------------------------------------------------------------
// route_kernel: 4-CTA cluster per batch element; all 3 iterations fused.
// blockIdx.x = b*QSPL + q. 320 threads: warp = class c, lane = capsule slot.
// ---------------------------------------------------------------------------
__global__ void __cluster_dims__(QSPL, 1, 1) __launch_bounds__(320, 3)
route_kernel(float* __restrict__ out)
{
    const int bid = blockIdx.x;
    const int b   = bid >> 2;
    const int q   = bid & (QSPL - 1);
    const int c   = threadIdx.x >> 5;
    const int ii  = threadIdx.x & 31;

    __shared__ float e_s[2][CCL][33];

    // q0 zeroes this batch's s-slots (3 iterations x 160 floats)
    if (q == 0) {
        for (int e = threadIdx.x; e < 3 * CCL * DOV; e += 320) {
            int t = e / (CCL * DOV);
            int j = e - t * (CCL * DOV);
            g_s[((size_t)t * BSZ + b) * CCL * DOV + j] = 0.0f;
        }
        __threadfence();
    }
    cluster_barrier();   // zeroing visible before any atomics

    const __half* ub = g_uhat + ((size_t)b * CCL + c) * (size_t)ICAP * DOV
                              + (size_t)(q * ISL + ii) * DOV;

    ull vrp[8];    // packed running vacc
    ull sacp[8];   // packed partial s accumulators

    #pragma unroll 1
    for (int t = 0; t < 3; t++) {
        #pragma unroll
        for (int j = 0; j < 8; j++) sacp[j] = pack2(0.0f, 0.0f);

        if (t == 0) {
            const ull w2 = pack2(0.1f, 0.1f);   // softmax of zeros over 10
            for (int ti = 0; ti < NT; ti++) {
                const uint4* p = reinterpret_cast<const uint4*>(
                    ub + (size_t)ti * 32 * DOV);
                uint4 A = p[0], B = p[1];
                const __half2* ha = reinterpret_cast<const __half2*>(&A);
                const __half2* hb = reinterpret_cast<const __half2*>(&B);
                #pragma unroll
                for (int k = 0; k < 4; k++) sacp[k]     = fma2(w2, h2f2(ha[k]), sacp[k]);
                #pragma unroll
                for (int k = 0; k < 4; k++) sacp[4 + k] = fma2(w2, h2f2(hb[k]), sacp[4 + k]);
            }
        } else {
            for (int ti = 0; ti < NT; ti++) {
                const uint4* p = reinterpret_cast<const uint4*>(
                    ub + (size_t)ti * 32 * DOV);
                uint4 A = p[0], B = p[1];
                const __half2* ha = reinterpret_cast<const __half2*>(&A);
                const __half2* hb = reinterpret_cast<const __half2*>(&B);

                ull d0 = mul2(h2f2(ha[0]), vrp[0]);
                ull d1 = mul2(h2f2(ha[1]), vrp[1]);
                d0 = fma2(h2f2(ha[2]), vrp[2], d0);
                d1 = fma2(h2f2(ha[3]), vrp[3], d1);
                d0 = fma2(h2f2(hb[0]), vrp[4], d0);
                d1 = fma2(h2f2(hb[1]), vrp[5], d1);
                d0 = fma2(h2f2(hb[2]), vrp[6], d0);
                d1 = fma2(h2f2(hb[3]), vrp[7], d1);
                d0 = add2(d0, d1);
                float lo, hi; unpack2(d0, lo, hi);

                // |logit| bounded (~35): exp safe in fp32 without max-subtract
                const int pb = ti & 1;
                e_s[pb][c][ii] = __expf(lo + hi);
                __syncthreads();

                float Z = e_s[pb][0][ii];
                #pragma unroll
                for (int cc = 1; cc < CCL; cc++) Z += e_s[pb][cc][ii];
                float w = __fdividef(e_s[pb][c][ii], Z);
                ull w2 = pack2(w, w);

                #pragma unroll
                for (int k = 0; k < 4; k++) sacp[k]     = fma2(w2, h2f2(ha[k]), sacp[k]);
                #pragma unroll
                for (int k = 0; k < 4; k++) sacp[4 + k] = fma2(w2, h2f2(hb[k]), sacp[4 + k]);
            }
        }

        // butterfly reduce partial s over 32 lanes
        float sac[DOV];
        #pragma unroll
        for (int j = 0; j < 8; j++) unpack2(sacp[j], sac[2 * j], sac[2 * j + 1]);
        #pragma unroll
        for (int off = 16; off > 0; off >>= 1)
            #pragma unroll
            for (int j = 0; j < DOV; j++)
                sac[j] += __shfl_xor_sync(0xffffffffu, sac[j], off);

        // cluster-wide s-sum through gmem atomics
        float* sp = g_s + (((size_t)t * BSZ + b) * CCL + c) * DOV;
        if (ii == 0) {
            #pragma unroll
            for (int j = 0; j < DOV; j++) atomicAdd(sp + j, sac[j]);
            __threadfence();
        }
        cluster_barrier();   // all 4 quarters' partials visible

        // identical squash in every CTA
        float s[DOV];
        #pragma unroll
        for (int j = 0; j < DOV; j++) s[j] = __ldcg(sp + j);
        float sq = 0.0f;
        #pragma unroll
        for (int j = 0; j < DOV; j++) sq = fmaf(s[j], s[j], sq);
        float scale = __fdividef(sqrtf(sq), 1.0f + sq);

        if (t == 2) {
            if (q == 0 && ii == 0) {
                float4* op = reinterpret_cast<float4*>(
                    out + ((size_t)b * CCL + c) * DOV);
                op[0] = make_float4(s[0]*scale,  s[1]*scale,  s[2]*scale,  s[3]*scale);
                op[1] = make_float4(s[4]*scale,  s[5]*scale,  s[6]*scale,  s[7]*scale);
                op[2] = make_float4(s[8]*scale,  s[9]*scale,  s[10]*scale, s[11]*scale);
                op[3] = make_float4(s[12]*scale, s[13]*scale, s[14]*scale, s[15]*scale);
            }
        } else if (t == 0) {
            #pragma unroll
            for (int j = 0; j < 8; j++)
                vrp[j] = pack2(s[2 * j] * scale, s[2 * j + 1] * scale);
        } else {
            float v0, v1;
            #pragma unroll
            for (int j = 0; j < 8; j++) {
                unpack2(vrp[j], v0, v1);
                vrp[j] = pack2(fmaf(s[2 * j], scale, v0),
                               fmaf(s[2 * j + 1], scale, v1));
            }
        }
    }
}

// ---------------------------------------------------------------------------
extern "C" void kernel_launch(void* const* d_in, const int* in_sizes, int n_in,
                              void* d_out, int out_size)
{
    const float* x = (const float*)d_in[0];
    const float* W = (const float*)d_in[1];
    if (in_sizes[0] == CCL * ICAP * DOV * DIV) {  // defensively identify by size
        const float* t = x; x = W; W = t;
    }
    float* out = (float*)d_out;

    uhat_kernel<<<ICAP, 256>>>(x, W);
    route_kernel<<<BSZ * QSPL, 320>>>(out);
}

// round 10
// speedup vs baseline: 1.2363x; 1.2363x over previous
#include <cuda_runtime.h>
#include <cuda_fp16.h>
#include <cstdint>

// DigitCapsules dynamic routing, GB300 sm_103a
// B=256, C=10, I=1152, DI=8, DO=16, 3 routing iterations.
//
// R10 = R4 route (best measured: 51.8us, prefetch + scalar fmaf, block=batch,
// warp=class) + FFMA2 uhat: W staged transposed [c][k][d] so LDS.128 (double2)
// gives {W_d, W_d+1} pairs feeding fma.rn.f32x2 directly; x broadcast {x_k,x_k}.
// Halves uhat's FMA-pipe work at the SAME LDS.128 count; bit-identical fp32.

#define BSZ  256
#define CCL  10
#define ICAP 1152
#define DOV  16
#define DIV  8
#define NT   (ICAP / 32)   // 36 tiles of 32 input capsules

typedef unsigned long long ull;

__device__ __align__(256) __half g_uhat[(size_t)BSZ * CCL * ICAP * DOV]; // 94.4 MB

// ---------------- packed f32x2 helpers (exact fp32 SIMD-2) ------------------
static __device__ __forceinline__ ull pack2(float x, float y) {
    ull r; asm("mov.b64 %0, {%1, %2};" : "=l"(r) : "f"(x), "f"(y)); return r;
}
static __device__ __forceinline__ void unpack2(ull v, float& x, float& y) {
    asm("mov.b64 {%0, %1}, %2;" : "=f"(x), "=f"(y) : "l"(v));
}
static __device__ __forceinline__ ull fma2(ull a, ull b, ull c) {
    ull d; asm("fma.rn.f32x2 %0, %1, %2, %3;" : "=l"(d) : "l"(a), "l"(b), "l"(c));
    return d;
}
static __device__ __forceinline__ unsigned int pack_h2(float a, float b) {
    __half2 h = __floats2half2_rn(a, b);
    return *reinterpret_cast<unsigned int*>(&h);
}

// ---------------------------------------------------------------------------
// K_uhat (FFMA2): u_hat[b,c,i,do] = sum_k W[c,i,0,do,k] * x[b,i,k]
// grid = I (block per input capsule), 256 threads = b.
// Ws transposed [c][k][d]: one LDS.128 (double2) = two {W_d,W_d+1} pairs.
// acc[j] accumulates dims (2j, 2j+1); k-order identical to the scalar
// version, so results are bit-identical fp32 before the single fp16 round.
// ---------------------------------------------------------------------------
__global__ __launch_bounds__(256) void uhat_kernel(
    const float* __restrict__ x, const float* __restrict__ W)
{
    const int i = blockIdx.x;
    const int b = threadIdx.x;

    __shared__ float Ws[CCL][DIV][DOV];   // [c][k][d] : 5120 B

    // Coalesced LDG: f = c*128 + d*8 + k is W's linear layout for this i.
    for (int f = threadIdx.x; f < CCL * DOV * DIV; f += 256) {
        int c   = f >> 7;
        int rem = f & 127;
        int d   = rem >> 3;
        int k   = rem & 7;
        Ws[c][k][d] = W[((size_t)c * ICAP + i) * (DOV * DIV) + rem];
    }

    const float* xp = x + (size_t)b * (ICAP * DIV) + (size_t)i * DIV;
    const float4 x0 = *reinterpret_cast<const float4*>(xp);
    const float4 x1 = *reinterpret_cast<const float4*>(xp + 4);
    ull xx[8];
    xx[0] = pack2(x0.x, x0.x); xx[1] = pack2(x0.y, x0.y);
    xx[2] = pack2(x0.z, x0.z); xx[3] = pack2(x0.w, x0.w);
    xx[4] = pack2(x1.x, x1.x); xx[5] = pack2(x1.y, x1.y);
    xx[6] = pack2(x1.z, x1.z); xx[7] = pack2(x1.w, x1.w);

    __syncthreads();

    __half* up = g_uhat + (size_t)b * (CCL * ICAP * DOV) + (size_t)i * DOV;

    #pragma unroll
    for (int c = 0; c < CCL; c++) {
        ull acc[8];
        #pragma unroll
        for (int j = 0; j < 8; j++) acc[j] = 0ULL;   // {0.0f, 0.0f}

        #pragma unroll
        for (int k = 0; k < DIV; k++) {
            const double2* wk = reinterpret_cast<const double2*>(&Ws[c][k][0]);
            double2 w0 = wk[0], w1 = wk[1], w2 = wk[2], w3 = wk[3];
            acc[0] = fma2(__double_as_longlong(w0.x), xx[k], acc[0]);
            acc[1] = fma2(__double_as_longlong(w0.y), xx[k], acc[1]);
            acc[2] = fma2(__double_as_longlong(w1.x), xx[k], acc[2]);
            acc[3] = fma2(__double_as_longlong(w1.y), xx[k], acc[3]);
            acc[4] = fma2(__double_as_longlong(w2.x), xx[k], acc[4]);
            acc[5] = fma2(__double_as_longlong(w2.y), xx[k], acc[5]);
            acc[6] = fma2(__double_as_longlong(w3.x), xx[k], acc[6]);
            acc[7] = fma2(__double_as_longlong(w3.y), xx[k], acc[7]);
        }

        unsigned int h[8];
        #pragma unroll
        for (int j = 0; j < 8; j++) {
            float lo, hi; unpack2(acc[j], lo, hi);
            h[j] = pack_h2(lo, hi);
        }
        __half* o = up + (size_t)c * (ICAP * DOV);
        *reinterpret_cast<uint4*>(o)     = make_uint4(h[0], h[1], h[2], h[3]);
        *reinterpret_cast<uint4*>(o + 8) = make_uint4(h[4], h[5], h[6], h[7]);
    }
}

// ---------------------------------------------------------------------------
// route_kernel: R4 version VERBATIM (best measured 51.8us).
// grid = B, 320 threads: warp = class, lane = i slot. 36 tiles, prefetch,
// double-buffered e_s, vacc in warp registers.
// ---------------------------------------------------------------------------
static __device__ __forceinline__ void unpack16(const uint4& a, const uint4& b,
                                                float* __restrict__ u) {
    const __half2* ha = reinterpret_cast<const __half2*>(&a);
    const __half2* hb = reinterpret_cast<const __half2*>(&b);
    #pragma unroll
    for (int q = 0; q < 4; q++) {
        float2 f = __half22float2(ha[q]);
        u[q * 2] = f.x; u[q * 2 + 1] = f.y;
    }
    #pragma unroll
    for (int q = 0; q < 4; q++) {
        float2 f = __half22float2(hb[q]);
        u[8 + q * 2] = f.x; u[8 + q * 2 + 1] = f.y;
    }
}

__global__ __launch_bounds__(320, 2) void route_kernel(float* __restrict__ out)
{
    const int b  = blockIdx.x;
    const int c  = threadIdx.x >> 5;
    const int ii = threadIdx.x & 31;

    __shared__ float e_s[2][CCL][33];

    const __half* ub = g_uhat + ((size_t)b * CCL + c) * (size_t)ICAP * DOV;

    float vr[DOV];
    #pragma unroll
    for (int j = 0; j < DOV; j++) vr[j] = 0.0f;

    float sac[DOV];

    // ---------------- iteration 0: uniform weights 0.1, no barriers
    #pragma unroll
    for (int j = 0; j < DOV; j++) sac[j] = 0.0f;
    {
        const uint4* p0 = reinterpret_cast<const uint4*>(ub + (size_t)ii * DOV);
        uint4 ua = p0[0], ux = p0[1];
        for (int ti = 0; ti < NT; ti++) {
            const int tn = (ti + 1 < NT) ? (ti + 1) : (NT - 1);
            const uint4* pn = reinterpret_cast<const uint4*>(
                ub + (size_t)(tn * 32 + ii) * DOV);
            uint4 na = pn[0], nb = pn[1];

            float u[DOV];
            unpack16(ua, ux, u);
            #pragma unroll
            for (int j = 0; j < DOV; j++) sac[j] = fmaf(0.1f, u[j], sac[j]);

            ua = na; ux = nb;
        }
    }
    #pragma unroll
    for (int off = 16; off > 0; off >>= 1)
        #pragma unroll
        for (int j = 0; j < DOV; j++)
            sac[j] += __shfl_xor_sync(0xffffffffu, sac[j], off);
    {
        float sq = 0.0f;
        #pragma unroll
        for (int j = 0; j < DOV; j++) sq = fmaf(sac[j], sac[j], sq);
        float scale = __fdividef(sqrtf(sq), 1.0f + sq);
        #pragma unroll
        for (int j = 0; j < DOV; j++) vr[j] = sac[j] * scale;
    }

    // ---------------- iterations 1 and 2
    #pragma unroll 1
    for (int t = 1; t < 3; t++) {
        #pragma unroll
        for (int j = 0; j < DOV; j++) sac[j] = 0.0f;

        const uint4* p0 = reinterpret_cast<const uint4*>(ub + (size_t)ii * DOV);
        uint4 ua = p0[0], ux = p0[1];

        for (int ti = 0; ti < NT; ti++) {
            const int tn = (ti + 1 < NT) ? (ti + 1) : (NT - 1);
            const uint4* pn = reinterpret_cast<const uint4*>(
                ub + (size_t)(tn * 32 + ii) * DOV);
            uint4 na = pn[0], nb = pn[1];

            float u[DOV];
            unpack16(ua, ux, u);

            float a = u[0] * vr[0];
            #pragma unroll
            for (int j = 1; j < DOV; j++) a = fmaf(u[j], vr[j], a);
            // |logit| bounded (~35): exp safe in fp32 without max-subtract
            float e = __expf(a);
            const int pb = ti & 1;
            e_s[pb][c][ii] = e;
            __syncthreads();
            float Z = e_s[pb][0][ii];
            #pragma unroll
            for (int cc = 1; cc < CCL; cc++) Z += e_s[pb][cc][ii];
            float w = __fdividef(e, Z);

            #pragma unroll
            for (int j = 0; j < DOV; j++) sac[j] = fmaf(w, u[j], sac[j]);

            ua = na; ux = nb;
        }

        #pragma unroll
        for (int off = 16; off > 0; off >>= 1)
            #pragma unroll
            for (int j = 0; j < DOV; j++)
                sac[j] += __shfl_xor_sync(0xffffffffu, sac[j], off);

        float sq = 0.0f;
        #pragma unroll
        for (int j = 0; j < DOV; j++) sq = fmaf(sac[j], sac[j], sq);
        float scale = __fdividef(sqrtf(sq), 1.0f + sq);

        if (t == 2) {
            if (ii == 0) {
                float4* op = reinterpret_cast<float4*>(
                    out + ((size_t)b * CCL + c) * DOV);
                op[0] = make_float4(sac[0]*scale,  sac[1]*scale,  sac[2]*scale,  sac[3]*scale);
                op[1] = make_float4(sac[4]*scale,  sac[5]*scale,  sac[6]*scale,  sac[7]*scale);
                op[2] = make_float4(sac[8]*scale,  sac[9]*scale,  sac[10]*scale, sac[11]*scale);
                op[3] = make_float4(sac[12]*scale, sac[13]*scale, sac[14]*scale, sac[15]*scale);
            }
        } else {
            #pragma unroll
            for (int j = 0; j < DOV; j++) vr[j] += sac[j] * scale;
        }
    }
}

// ---------------------------------------------------------------------------
extern "C" void kernel_launch(void* const* d_in, const int* in_sizes, int n_in,
                              void* d_out, int out_size)
{
    const float* x = (const float*)d_in[0];
    const float* W = (const float*)d_in[1];
    if (in_sizes[0] == CCL * ICAP * DOV * DIV) {  // defensively identify by size
        const float* t = x; x = W; W = t;
    }
    float* out = (float*)d_out;

    uhat_kernel<<<ICAP, 256>>>(x, W);
    route_kernel<<<BSZ, 320>>>(out);
}